// round 17
// baseline (speedup 1.0000x reference)
#include <cuda_runtime.h>
#include <cuda_bf16.h>
#include <math_constants.h>

// ExactScoreNetwork: out[b,d] = sqrt(1-e_b) * sum_k p_bk * (x_bd - a_b*c_kd) / v_bkd
//   e = exp(-Beta(t)), a = sqrt(e), v = 1 + e*(s^2 - 1)
//   p_bk = softmax_k( -0.5*sum_d diff^2/v - 128*sum_d ln v + ln w_k )
//
// CTA = 64 threads (2 warps) handles 2 batch rows; warp w does K-half [w*64,+64).
// Center/u loads shared across both rows (register reuse, halves L1 LDG traffic);
// 4096 warps total for occupancy; K-half softmax states merge via smem at the end.
// Scalar f32 math (R16 f32x2 experiment regressed: pack/unpack latency + regs).
// Softmax rescale is a RARE warp-uniform branch (common path: 1 fma/elem).
// Warp reduction: fused 2-value tree (8 shfl instead of 20).

constexpr int K_COMP = 128;
constexpr int D_DIM  = 256;
constexpr int KHALF  = K_COMP / 2;

__device__ float g_u[K_COMP * D_DIM];   // stds^2 - 1
__device__ float g_lw2[K_COMP];         // log2(weights)

__device__ __forceinline__ float frcp(float x){ float r; asm("rcp.approx.ftz.f32 %0, %1;" : "=f"(r) : "f"(x)); return r; }
__device__ __forceinline__ float flg2(float x){ float r; asm("lg2.approx.ftz.f32 %0, %1;" : "=f"(r) : "f"(x)); return r; }
__device__ __forceinline__ float fex2(float x){ float r; asm("ex2.approx.ftz.f32 %0, %1;" : "=f"(r) : "f"(x)); return r; }

// accurate-ish log2: split exponent, lg2.approx on mantissa in [1,2)
__device__ __forceinline__ float log2_acc(float p){
    int b = __float_as_int(p);
    float m = __int_as_float((b & 0x007FFFFF) | 0x3F800000);
    return (float)((b >> 23) - 127) + flg2(m);
}

__global__ void prep_kernel(const float* __restrict__ stds, const float* __restrict__ weights)
{
    int i = blockIdx.x * blockDim.x + threadIdx.x;      // 0 .. K*D-1
    float s = stds[i];
    g_u[i] = fmaf(s, s, -1.0f);
    if (i < K_COMP) g_lw2[i] = log2f(weights[i]);
}

__global__ void __launch_bounds__(64)
score_kernel(const float* __restrict__ x, const float* __restrict__ t,
             const float* __restrict__ centers, float* __restrict__ out)
{
    __shared__ float s_acc[2][32][8];
    __shared__ float s_mx[2], s_den[2];

    const int lane = threadIdx.x & 31;
    const int w    = threadIdx.x >> 5;          // warp id in CTA: K-half selector
    const int b0   = blockIdx.x * 2;            // two rows per CTA

    // per-row scalars (both warps compute both rows)
    float ev[2], na[2], osc[2];
    float xr[2][8], acc[2][8], mx[2], den[2];
    #pragma unroll
    for (int r = 0; r < 2; r++) {
        float tt = t[b0 + r];
        float Bt = fmaf(9.95f, tt * tt, 0.1f * tt);   // Beta(t) = 0.1 t + 9.95 t^2
        float e  = expf(-Bt);                          // accurate: matters for 1-e at small t
        ev[r]  = e;
        na[r]  = -sqrtf(e);                            // -a
        osc[r] = sqrtf(fmaxf(1.0f - e, 0.0f));
        const float4* xp = reinterpret_cast<const float4*>(x + (size_t)(b0 + r) * D_DIM + lane * 8);
        float4 x0 = xp[0], x1 = xp[1];
        xr[r][0]=x0.x; xr[r][1]=x0.y; xr[r][2]=x0.z; xr[r][3]=x0.w;
        xr[r][4]=x1.x; xr[r][5]=x1.y; xr[r][6]=x1.z; xr[r][7]=x1.w;
        #pragma unroll
        for (int j = 0; j < 8; j++) acc[r][j] = 0.0f;
        mx[r]  = -CUDART_INF_F;                        // log2-domain running max
        den[r] = 0.0f;
    }

    const int kbeg = w * KHALF;
    #pragma unroll 1
    for (int k = kbeg; k < kbeg + KHALF; k++) {
        const float4* cp = reinterpret_cast<const float4*>(centers + (size_t)k * D_DIM + lane * 8);
        const float4* up = reinterpret_cast<const float4*>(g_u     + (size_t)k * D_DIM + lane * 8);
        float4 c0 = __ldg(cp), c1 = __ldg(cp + 1);
        float4 u0 = __ldg(up), u1 = __ldg(up + 1);
        float c[8] = {c0.x,c0.y,c0.z,c0.w,c1.x,c1.y,c1.z,c1.w};
        float u[8] = {u0.x,u0.y,u0.z,u0.w,u1.x,u1.y,u1.z,u1.w};
        float lw2 = g_lw2[k];

        // both rows share c/u; interleaved for ILP
        float g[2][8];
        float q0 = 0.0f, q1 = 0.0f, pr0 = 1.0f, pr1 = 1.0f;
        #pragma unroll
        for (int j = 0; j < 8; j++) {
            float v0  = fmaf(ev[0], u[j], 1.0f);       // in [0.25, 1]
            float v1  = fmaf(ev[1], u[j], 1.0f);
            float rv0 = frcp(v0);
            float rv1 = frcp(v1);
            float d0  = fmaf(na[0], c[j], xr[0][j]);
            float d1  = fmaf(na[1], c[j], xr[1][j]);
            float g0  = d0 * rv0;
            float g1  = d1 * rv1;
            q0 = fmaf(d0, g0, q0);                     // sum diff^2 / v
            q1 = fmaf(d1, g1, q1);
            pr0 *= v0;                                 // chunk product for log-det
            pr1 *= v1;
            g[0][j] = g0;                              // diff / v (grad piece)
            g[1][j] = g1;
        }
        // per-lane combined log2-domain partial: z = -0.5*log2e*q - 128*log2(prod)
        float z0 = fmaf(-0.72134752044448170f, q0, -128.0f * log2_acc(pr0));
        float z1 = fmaf(-0.72134752044448170f, q1, -128.0f * log2_acc(pr1));

        // fused 2-value tree reduction: fold rows into warp halves, reduce, broadcast
        float t0 = __shfl_xor_sync(0xffffffffu, z0, 16);
        float t1 = __shfl_xor_sync(0xffffffffu, z1, 16);
        float wv = (lane < 16) ? (z0 + t0) : (z1 + t1);
        wv += __shfl_xor_sync(0xffffffffu, wv, 8);
        wv += __shfl_xor_sync(0xffffffffu, wv, 4);
        wv += __shfl_xor_sync(0xffffffffu, wv, 2);
        wv += __shfl_xor_sync(0xffffffffu, wv, 1);
        float lp0 = __shfl_sync(0xffffffffu, wv, 0)  + lw2;
        float lp1 = __shfl_sync(0xffffffffu, wv, 16) + lw2;

        // rare warp-uniform rescale (E[#max-updates] ~ ln K); common path is cheap
        if (lp0 > mx[0] || lp1 > mx[1]) {
            float nm0 = fmaxf(mx[0], lp0), nm1 = fmaxf(mx[1], lp1);
            float sc0 = fex2(mx[0] - nm0);             // ex2(-inf)=0 on first k
            float sc1 = fex2(mx[1] - nm1);
            den[0] *= sc0;
            den[1] *= sc1;
            #pragma unroll
            for (int j = 0; j < 8; j++) {
                acc[0][j] *= sc0;
                acc[1][j] *= sc1;
            }
            mx[0] = nm0; mx[1] = nm1;
        }
        float p0 = fex2(lp0 - mx[0]);
        float p1 = fex2(lp1 - mx[1]);
        den[0] += p0;
        den[1] += p1;
        #pragma unroll
        for (int j = 0; j < 8; j++) {
            acc[0][j] = fmaf(p0, g[0][j], acc[0][j]);  // softmax-weighted grad accum
            acc[1][j] = fmaf(p1, g[1][j], acc[1][j]);
        }
    }

    // ── merge the two K-half states ──
    // warp w merges row (rm = w); it exports its OTHER row (ro = 1-w) to smem slot w.
    const int rm = w, ro = 1 - w;
    #pragma unroll
    for (int j = 0; j < 8; j++) s_acc[w][lane][j] = acc[ro][j];
    if (lane == 0) { s_mx[w] = mx[ro]; s_den[w] = den[ro]; }
    __syncthreads();

    float omx  = s_mx[ro];                 // partner warp's state for row rm
    float oden = s_den[ro];
    float mn = fmaxf(mx[rm], omx);
    float sa = fex2(mx[rm] - mn);
    float sb = fex2(omx - mn);
    float dtot = fmaf(den[rm], sa, oden * sb);
    float s = osc[rm] * frcp(dtot);

    float4 o0, o1;
    float oacc[8];
    #pragma unroll
    for (int j = 0; j < 8; j++)
        oacc[j] = fmaf(acc[rm][j], sa, s_acc[ro][lane][j] * sb) * s;
    o0.x = oacc[0]; o0.y = oacc[1]; o0.z = oacc[2]; o0.w = oacc[3];
    o1.x = oacc[4]; o1.y = oacc[5]; o1.z = oacc[6]; o1.w = oacc[7];
    float4* op = reinterpret_cast<float4*>(out + (size_t)(b0 + rm) * D_DIM + lane * 8);
    op[0] = o0; op[1] = o1;
}

extern "C" void kernel_launch(void* const* d_in, const int* in_sizes, int n_in,
                              void* d_out, int out_size)
{
    const float* x       = (const float*)d_in[0];   // [B, 256]
    const float* t       = (const float*)d_in[1];   // [B]
    const float* centers = (const float*)d_in[2];   // [128, 256]
    const float* stds    = (const float*)d_in[3];   // [128, 256]
    const float* weights = (const float*)d_in[4];   // [128]
    float* out = (float*)d_out;                      // [B, 256]

    int B = in_sizes[1];                             // t element count

    prep_kernel<<<(K_COMP * D_DIM) / 128, 128>>>(stds, weights);
    score_kernel<<<B / 2, 64>>>(x, t, centers, out);
}